// round 1
// baseline (speedup 1.0000x reference)
#include <cuda_runtime.h>

#define N_NODES 100000
#define N_EDGES 1600000
#define IN_DIM 128
#define HID_DIM 64
#define OUT_DIM 64
#define EPS 0.1f

// ---------------- device scratch (allowed: __device__ globals) ----------------
struct Edge { int s; float nm; };

__device__ float g_h0[(size_t)N_NODES * HID_DIM];   // 25.6 MB
__device__ float g_h1[(size_t)N_NODES * HID_DIM];   // 25.6 MB
__device__ float g_dinv[N_NODES];
__device__ float g_selfc[N_NODES];
__device__ int   g_count[N_NODES];
__device__ int   g_fill[N_NODES];
__device__ int   g_rowptr[N_NODES];
__device__ Edge  g_edges[N_EDGES];                  // 12.8 MB

#define SCAN_ELEMS 2048
#define SCAN_NBLK ((N_NODES + SCAN_ELEMS - 1) / SCAN_ELEMS)  // 49
__device__ int g_bsum[SCAN_NBLK];
__device__ int g_boff[SCAN_NBLK];

// ---------------- CSR build ----------------

__global__ void k_zero() {
    int i = blockIdx.x * blockDim.x + threadIdx.x;
    if (i < N_NODES) { g_count[i] = 0; g_fill[i] = 0; }
}

__global__ void k_degree(const int* __restrict__ dst) {
    int e = blockIdx.x * blockDim.x + threadIdx.x;
    if (e < N_EDGES) atomicAdd(&g_count[dst[e]], 1);
}

__global__ void k_dinv() {
    int i = blockIdx.x * blockDim.x + threadIdx.x;
    if (i >= N_NODES) return;
    float deg = (float)g_count[i] + 2.0f;   // self-loop weight 2.0 (improved=True)
    float di = rsqrtf(deg);
    g_dinv[i] = di;
    // h' = (1 - eps * 2*dinv^2) * h - eps * sum(edges)
    g_selfc[i] = 1.0f - EPS * 2.0f * di * di;
}

__global__ void k_scan_reduce() {
    int b = blockIdx.x, t = threadIdx.x;
    int base = b * SCAN_ELEMS + t * 8;
    int s = 0;
#pragma unroll
    for (int j = 0; j < 8; j++) { int i = base + j; if (i < N_NODES) s += g_count[i]; }
#pragma unroll
    for (int o = 16; o > 0; o >>= 1) s += __shfl_down_sync(0xFFFFFFFFu, s, o);
    __shared__ int ws[8];
    if ((t & 31) == 0) ws[t >> 5] = s;
    __syncthreads();
    if (t == 0) {
        int tot = 0;
#pragma unroll
        for (int i = 0; i < 8; i++) tot += ws[i];
        g_bsum[b] = tot;
    }
}

__global__ void k_scan_mid() {
    int run = 0;
    for (int i = 0; i < SCAN_NBLK; i++) { g_boff[i] = run; run += g_bsum[i]; }
}

__global__ void k_scan_write() {
    __shared__ int warp_sums[8];
    int b = blockIdx.x, t = threadIdx.x;
    int base = b * SCAN_ELEMS + t * 8;
    int v[8];
    int tsum = 0;
#pragma unroll
    for (int j = 0; j < 8; j++) {
        int i = base + j;
        int c = (i < N_NODES) ? g_count[i] : 0;
        v[j] = tsum;        // thread-local exclusive prefix
        tsum += c;
    }
    int lane = t & 31, w = t >> 5;
    int inc = tsum;
#pragma unroll
    for (int o = 1; o < 32; o <<= 1) {
        int nv = __shfl_up_sync(0xFFFFFFFFu, inc, o);
        if (lane >= o) inc += nv;
    }
    int warp_excl = inc - tsum;
    if (lane == 31) warp_sums[w] = inc;
    __syncthreads();
    int woff = 0;
    for (int i = 0; i < w; i++) woff += warp_sums[i];
    int toff = woff + warp_excl + g_boff[b];
#pragma unroll
    for (int j = 0; j < 8; j++) {
        int i = base + j;
        if (i < N_NODES) g_rowptr[i] = toff + v[j];
    }
}

__global__ void k_scatter(const int* __restrict__ src, const int* __restrict__ dst) {
    int e = blockIdx.x * blockDim.x + threadIdx.x;
    if (e >= N_EDGES) return;
    int s = src[e], d = dst[e];
    int pos = g_rowptr[d] + atomicAdd(&g_fill[d], 1);
    Edge ed;
    ed.s = s;
    ed.nm = g_dinv[s] * g_dinv[d];
    g_edges[pos] = ed;
}

// ---------------- GEMM1: h0 = x @ emb_w + emb_b   [N,128]x[128,64] ----------------
// 32 rows/block, 256 threads: 8 threads/row, 8 cols/thread. W + x-tile in smem (48KB).

__global__ void k_gemm1(const float* __restrict__ x,
                        const float* __restrict__ w,
                        const float* __restrict__ b) {
    extern __shared__ float sm[];
    float* Ws = sm;                    // 128*64 = 8192 floats (32KB)
    float* Xs = sm + IN_DIM * HID_DIM; // 32*128 = 4096 floats (16KB)
    int t = threadIdx.x;
    int rowbase = blockIdx.x * 32;

    float4* Ws4 = (float4*)Ws;
    const float4* w4 = (const float4*)w;
#pragma unroll
    for (int i = t; i < IN_DIM * HID_DIM / 4; i += 256) Ws4[i] = w4[i];

    float4* Xs4 = (float4*)Xs;
    const float4* x4 = (const float4*)(x + (size_t)rowbase * IN_DIM);
#pragma unroll
    for (int i = t; i < 32 * IN_DIM / 4; i += 256) Xs4[i] = x4[i];
    __syncthreads();

    int rl = t >> 3;
    int cg = (t & 7) * 8;
    float acc[8];
#pragma unroll
    for (int j = 0; j < 8; j++) acc[j] = 0.0f;

    const float* xr = Xs + rl * IN_DIM;
#pragma unroll 4
    for (int k = 0; k < IN_DIM; k++) {
        float xv = xr[k];
        const float4* wr = (const float4*)(Ws + k * HID_DIM + cg);
        float4 w0 = wr[0], w1 = wr[1];
        acc[0] = fmaf(xv, w0.x, acc[0]); acc[1] = fmaf(xv, w0.y, acc[1]);
        acc[2] = fmaf(xv, w0.z, acc[2]); acc[3] = fmaf(xv, w0.w, acc[3]);
        acc[4] = fmaf(xv, w1.x, acc[4]); acc[5] = fmaf(xv, w1.y, acc[5]);
        acc[6] = fmaf(xv, w1.z, acc[6]); acc[7] = fmaf(xv, w1.w, acc[7]);
    }
    float4 o0, o1;
    o0.x = acc[0] + __ldg(&b[cg + 0]); o0.y = acc[1] + __ldg(&b[cg + 1]);
    o0.z = acc[2] + __ldg(&b[cg + 2]); o0.w = acc[3] + __ldg(&b[cg + 3]);
    o1.x = acc[4] + __ldg(&b[cg + 4]); o1.y = acc[5] + __ldg(&b[cg + 5]);
    o1.z = acc[6] + __ldg(&b[cg + 6]); o1.w = acc[7] + __ldg(&b[cg + 7]);
    float* out = g_h0 + (size_t)(rowbase + rl) * HID_DIM + cg;
    ((float4*)out)[0] = o0;
    ((float4*)out)[1] = o1;
}

// ---------------- SpMM pull: one warp per node, float2 per lane ----------------

__global__ void k_spmm(int flip) {
    const float* hin = flip ? g_h1 : g_h0;
    float*       hout = flip ? g_h0 : g_h1;

    int gw = (blockIdx.x * blockDim.x + threadIdx.x) >> 5;
    if (gw >= N_NODES) return;
    int lane = threadIdx.x & 31;

    int start = g_rowptr[gw];
    int len = g_count[gw];
    const float2* h2 = (const float2*)hin;
    const int2* ebase = (const int2*)g_edges;

    float ax = 0.0f, ay = 0.0f;
#pragma unroll 4
    for (int k = 0; k < len; k++) {
        int2 ed = __ldg(&ebase[start + k]);
        float nm = __int_as_float(ed.y);
        float2 v = __ldg(&h2[(size_t)ed.x * 32 + lane]);
        ax = fmaf(nm, v.x, ax);
        ay = fmaf(nm, v.y, ay);
    }
    float2 hv = h2[(size_t)gw * 32 + lane];
    float c = g_selfc[gw];
    float2 o;
    o.x = c * hv.x - EPS * ax;
    o.y = c * hv.y - EPS * ay;
    ((float2*)hout)[(size_t)gw * 32 + lane] = o;
}

// ---------------- GEMM2: out = tanh(h0) @ ro_w + ro_b   [N,64]x[64,64] ----------------
// 64 rows/block, 256 threads: 4 threads/row, 16 cols/thread. tanh fused in tile load.

__global__ void k_gemm2(const float* __restrict__ w,
                        const float* __restrict__ b,
                        float* __restrict__ out) {
    __shared__ float Ws[HID_DIM * OUT_DIM];  // 16KB
    __shared__ float Xs[64 * HID_DIM];       // 16KB
    int t = threadIdx.x;
    int rowbase = blockIdx.x * 64;

#pragma unroll
    for (int i = t; i < HID_DIM * OUT_DIM / 4; i += 256)
        ((float4*)Ws)[i] = ((const float4*)w)[i];

    const int QW = HID_DIM / 4;  // float4s per row = 16
    for (int i = t; i < 64 * QW; i += 256) {
        int row = rowbase + i / QW;
        float4 v = make_float4(0.f, 0.f, 0.f, 0.f);
        if (row < N_NODES)
            v = ((const float4*)g_h0)[(size_t)row * QW + (i % QW)];
        v.x = tanhf(v.x); v.y = tanhf(v.y); v.z = tanhf(v.z); v.w = tanhf(v.w);
        ((float4*)Xs)[i] = v;
    }
    __syncthreads();

    int rl = t >> 2;
    int cg = (t & 3) * 16;
    int row = rowbase + rl;
    if (row >= N_NODES) return;

    float acc[16];
#pragma unroll
    for (int j = 0; j < 16; j++) acc[j] = 0.0f;

    const float* xr = Xs + rl * HID_DIM;
#pragma unroll 4
    for (int k = 0; k < HID_DIM; k++) {
        float xv = xr[k];
        const float4* wr = (const float4*)(Ws + k * OUT_DIM + cg);
#pragma unroll
        for (int q = 0; q < 4; q++) {
            float4 wv = wr[q];
            acc[q * 4 + 0] = fmaf(xv, wv.x, acc[q * 4 + 0]);
            acc[q * 4 + 1] = fmaf(xv, wv.y, acc[q * 4 + 1]);
            acc[q * 4 + 2] = fmaf(xv, wv.z, acc[q * 4 + 2]);
            acc[q * 4 + 3] = fmaf(xv, wv.w, acc[q * 4 + 3]);
        }
    }
    float* o = out + (size_t)row * OUT_DIM + cg;
#pragma unroll
    for (int q = 0; q < 4; q++) {
        float4 ov;
        ov.x = acc[q * 4 + 0] + __ldg(&b[cg + q * 4 + 0]);
        ov.y = acc[q * 4 + 1] + __ldg(&b[cg + q * 4 + 1]);
        ov.z = acc[q * 4 + 2] + __ldg(&b[cg + q * 4 + 2]);
        ov.w = acc[q * 4 + 3] + __ldg(&b[cg + q * 4 + 3]);
        ((float4*)o)[q] = ov;
    }
}

// ---------------- launch ----------------

extern "C" void kernel_launch(void* const* d_in, const int* in_sizes, int n_in,
                              void* d_out, int out_size) {
    const float* x     = (const float*)d_in[0];
    const int*   ei    = (const int*)d_in[1];
    const float* emb_w = (const float*)d_in[2];
    const float* emb_b = (const float*)d_in[3];
    const float* ro_w  = (const float*)d_in[4];
    const float* ro_b  = (const float*)d_in[5];
    float* out = (float*)d_out;

    const int* src = ei;            // edge_index[0]
    const int* dst = ei + N_EDGES;  // edge_index[1]

    const int NB_N = (N_NODES + 255) / 256;   // 391
    const int NB_E = (N_EDGES + 255) / 256;   // 6250

    // CSR-by-dst build
    k_zero<<<NB_N, 256>>>();
    k_degree<<<NB_E, 256>>>(dst);
    k_dinv<<<NB_N, 256>>>();
    k_scan_reduce<<<SCAN_NBLK, 256>>>();
    k_scan_mid<<<1, 1>>>();
    k_scan_write<<<SCAN_NBLK, 256>>>();
    k_scatter<<<NB_E, 256>>>(src, dst);

    // h0 = x @ emb_w + emb_b
    k_gemm1<<<N_NODES / 32, 256, 49152>>>(x, emb_w, emb_b);

    // 4 propagation iterations, ping-pong h0 <-> h1 (ends in h0)
    const int SPMM_BLOCKS = (N_NODES * 32 + 255) / 256;  // 12500
    k_spmm<<<SPMM_BLOCKS, 256>>>(0);
    k_spmm<<<SPMM_BLOCKS, 256>>>(1);
    k_spmm<<<SPMM_BLOCKS, 256>>>(0);
    k_spmm<<<SPMM_BLOCKS, 256>>>(1);

    // out = tanh(h0) @ ro_w + ro_b
    k_gemm2<<<(N_NODES + 63) / 64, 256>>>(ro_w, ro_b, out);
}